// round 11
// baseline (speedup 1.0000x reference)
#include <cuda_runtime.h>
#include <cstdint>

#define B_ 8
#define C_ 64
#define H_ 256
#define W_ 256
#define HW_ (H_ * W_)
#define TH 4                  // output rows per block
#define ROWS (TH + 2)         // staged input rows (with halo)
#define NS 6                  // ring buffers
#define PD 4                  // prefetch depth (channels staged ahead)
#define RSTRIDE 264           // idx3 = left zero guard, 4..259 = data, 260 = right zero guard
#define FULLMASK 0xffffffffu

__device__ __forceinline__ void cp16(uint32_t dst, const float* src) {
    asm volatile("cp.async.cg.shared.global [%0], [%1], 16;" :: "r"(dst), "l"(src));
}
__device__ __forceinline__ void cp_commit() {
    asm volatile("cp.async.commit_group;");
}
__device__ __forceinline__ void cp_wait3() {
    asm volatile("cp.async.wait_group 3;");
}

__global__ __launch_bounds__(256, 4)
void conv_attn_v11(const float* __restrict__ q, const float* __restrict__ k,
                   const float* __restrict__ v, float* __restrict__ out)
{
    __shared__ __align__(16) float ring[NS][ROWS][RSTRIDE];

    const int tid  = threadIdx.x;
    const int lane = tid & 31;
    const int x    = tid & 63;         // 64 groups of 4 px; warp = 128 contiguous px of one row
    const int y    = tid >> 6;         // output row 0..3
    const int w0   = x * 4;
    const int h0   = blockIdx.x * TH;
    const int b    = blockIdx.y;

    const size_t cb = (size_t)b * C_ * HW_;
    const float* qb = q + cb;
    const float* kb = k + cb;
    const float* vb = v + cb;
    float*       ob = out + cb;
    const int rowoff = (h0 + y) * W_ + w0;

    // zero guard cells once (never overwritten by staging)
    for (int i = tid; i < NS * ROWS; i += 256) {
        ring[i / ROWS][i % ROWS][3]   = 0.0f;
        ring[i / ROWS][i % ROWS][260] = 0.0f;
    }

    const uint32_t ring_s = (uint32_t)__cvta_generic_to_shared(&ring[0][0][0]);

    // stage channel c of tensor `srcb` into ring[c % NS]
    auto stage = [&](const float* srcb, int c) {
        const int      bi   = c % NS;
        const uint32_t bufb = ring_s + (uint32_t)bi * (ROWS * RSTRIDE * 4);
        const float*   chan = srcb + (size_t)c * HW_;
        #pragma unroll
        for (int slot = tid; slot < ROWS * 64; slot += 256) {
            const int r   = slot >> 6;
            const int col = (slot & 63) * 4;
            const int hh  = h0 - 1 + r;
            if (hh >= 0 && hh < H_) {
                cp16(bufb + (uint32_t)(r * RSTRIDE + 4 + col) * 4, chan + hh * W_ + col);
            } else {
                float4 z = make_float4(0.f, 0.f, 0.f, 0.f);
                *reinterpret_cast<float4*>(&ring[bi][r][4 + col]) = z;
            }
        }
    };

    float s[4][9];
#pragma unroll
    for (int j = 0; j < 4; j++)
#pragma unroll
        for (int i = 0; i < 9; i++) s[j][i] = 0.0f;

    // ================= Pass 1: scores =================
    stage(kb, 0); cp_commit();
    stage(kb, 1); cp_commit();
    stage(kb, 2); cp_commit();
    stage(kb, 3); cp_commit();
    float4 qcur = *reinterpret_cast<const float4*>(qb + rowoff);

    int bi = 0;
#pragma unroll 1
    for (int c = 0; c < C_; c++) {
        cp_wait3();              // channel c's group complete (4 pending -> 3)
        __syncthreads();         // single barrier: also orders last iter's reads before this iter's stage

        // branchless q prefetch for next channel
        const int cn = (c + 1 < C_) ? (c + 1) : (C_ - 1);
        const float4 qnext = *reinterpret_cast<const float4*>(qb + (size_t)cn * HW_ + rowoff);

        const float qa[4] = {qcur.x, qcur.y, qcur.z, qcur.w};
#pragma unroll
        for (int dy = 0; dy < 3; dy++) {
            const float* rp = &ring[bi][y + dy][4 + w0];
            const float4 m = *reinterpret_cast<const float4*>(rp);
            float lft = __shfl_up_sync(FULLMASK, m.w, 1);
            float rgt = __shfl_down_sync(FULLMASK, m.x, 1);
            if (lane == 0)  lft = rp[-1];   // guard cell gives 0 at w=0
            if (lane == 31) rgt = rp[4];    // guard cell gives 0 at w=255

            const float a[6] = {lft, m.x, m.y, m.z, m.w, rgt};
#pragma unroll
            for (int j = 0; j < 4; j++)
#pragma unroll
                for (int dx = 0; dx < 3; dx++)
                    s[j][dy * 3 + dx] = fmaf(qa[j], a[j + dx], s[j][dy * 3 + dx]);
        }

        // stage channel c+PD (buffer last read 2 iters ago; safe past this iter's sync)
        if (c + PD < C_) stage(kb, c + PD);
        cp_commit();             // empty group on tail iters keeps wait accounting uniform
        qcur = qnext;
        bi = (bi + 1 == NS) ? 0 : bi + 1;
    }
    __syncthreads();             // protect ring before pass-2 prologue overwrites it

    // ================= Softmax over 9 taps (OOB taps = score 0, zero-pad semantics) =================
#pragma unroll
    for (int j = 0; j < 4; j++) {
        float mx = s[j][0];
#pragma unroll
        for (int i = 1; i < 9; i++) mx = fmaxf(mx, s[j][i]);
        float sum = 0.0f;
#pragma unroll
        for (int i = 0; i < 9; i++) { s[j][i] = __expf(s[j][i] - mx); sum += s[j][i]; }
        const float inv = 1.0f / sum;
#pragma unroll
        for (int i = 0; i < 9; i++) s[j][i] *= inv;
    }

    // ================= Pass 2: weighted v sum =================
    stage(vb, 0); cp_commit();
    stage(vb, 1); cp_commit();
    stage(vb, 2); cp_commit();
    stage(vb, 3); cp_commit();

    bi = 0;
#pragma unroll 1
    for (int c = 0; c < C_; c++) {
        cp_wait3();
        __syncthreads();

        float acc[4] = {0.f, 0.f, 0.f, 0.f};
#pragma unroll
        for (int dy = 0; dy < 3; dy++) {
            const float* rp = &ring[bi][y + dy][4 + w0];
            const float4 m = *reinterpret_cast<const float4*>(rp);
            float lft = __shfl_up_sync(FULLMASK, m.w, 1);
            float rgt = __shfl_down_sync(FULLMASK, m.x, 1);
            if (lane == 0)  lft = rp[-1];
            if (lane == 31) rgt = rp[4];

            const float a[6] = {lft, m.x, m.y, m.z, m.w, rgt};
#pragma unroll
            for (int j = 0; j < 4; j++)
#pragma unroll
                for (int dx = 0; dx < 3; dx++)
                    acc[j] = fmaf(s[j][dy * 3 + dx], a[j + dx], acc[j]);
        }

        if (c + PD < C_) stage(vb, c + PD);
        cp_commit();

        float4 o;
        o.x = acc[0]; o.y = acc[1]; o.z = acc[2]; o.w = acc[3];
        *reinterpret_cast<float4*>(ob + (size_t)c * HW_ + rowoff) = o;
        bi = (bi + 1 == NS) ? 0 : bi + 1;
    }
}

extern "C" void kernel_launch(void* const* d_in, const int* in_sizes, int n_in,
                              void* d_out, int out_size)
{
    const float* q = (const float*)d_in[0];
    const float* k = (const float*)d_in[1];
    const float* v = (const float*)d_in[2];
    float* out = (float*)d_out;

    dim3 block(256);
    dim3 grid(H_ / TH, B_);     // 64 x 8 = 512 blocks
    conv_attn_v11<<<grid, block>>>(q, k, v, out);
}